// round 8
// baseline (speedup 1.0000x reference)
#include <cuda_runtime.h>
#include <cuda_bf16.h>
#include <cstdint>
#include <math.h>

#define N_RAYS 262144
#define HASHMAP_SIZE 524288
#define HMASK 0x7FFFFu
#define DIM 256
#define N_MID 6
#define PRIME1 2654435761u

#define TILE_M 64
#define NCTAS (N_RAYS / TILE_M)    // 4096
#define SA 272                      // A digit row stride (bytes): conflict-free ldmatrix

// packed weight fragments: uint4 = {bh0, bh1, bl0, bl1} per (layer, kslab, ntile, lane)
// mid: [6][8][32][32], in: [1][32][32] (kslab 0 only, k>=16 zero)
#define PKM_TOT (N_MID * 8 * 32 * 32)   // 49152
__device__ uint4 g_pkm[PKM_TOT];
__device__ uint4 g_pki[32 * 32];
__device__ int g_wmax[7];               // float-bits, atomicMax-built (deterministic)

__device__ __forceinline__ uint32_t smem_u32(const void* p) {
    uint32_t a;
    asm("{ .reg .u64 t; cvta.to.shared.u64 t, %1; cvt.u32.u64 %0, t; }" : "=r"(a) : "l"(p));
    return a;
}

#define MMA_U8S8(d, a, b0v, b1v) \
    asm volatile("mma.sync.aligned.m16n8k32.row.col.s32.u8.s8.s32 " \
        "{%0,%1,%2,%3},{%4,%5,%6,%7},{%8,%9},{%0,%1,%2,%3};" \
        : "+r"((d)[0]), "+r"((d)[1]), "+r"((d)[2]), "+r"((d)[3]) \
        : "r"((a)[0]), "r"((a)[1]), "r"((a)[2]), "r"((a)[3]), "r"(b0v), "r"(b1v))
#define MMA_S8S8(d, a, b0v, b1v) \
    asm volatile("mma.sync.aligned.m16n8k32.row.col.s32.s8.s8.s32 " \
        "{%0,%1,%2,%3},{%4,%5,%6,%7},{%8,%9},{%0,%1,%2,%3};" \
        : "+r"((d)[0]), "+r"((d)[1]), "+r"((d)[2]), "+r"((d)[3]) \
        : "r"((a)[0]), "r"((a)[1]), "r"((a)[2]), "r"((a)[3]), "r"(b0v), "r"(b1v))
#define LDSM4(r, addr) \
    asm volatile("ldmatrix.sync.aligned.m8n8.x4.shared.b16 {%0,%1,%2,%3}, [%4];" \
        : "=r"((r)[0]), "=r"((r)[1]), "=r"((r)[2]), "=r"((r)[3]) : "r"(addr))

// ---------------- per-layer weight max ----------------
__global__ __launch_bounds__(256) void wmax_kernel(
    const float* __restrict__ Wmid, const float* __restrict__ Win)
{
    __shared__ float red[256];
    int b = blockIdx.x, t = threadIdx.x;
    float m = 0.0f;
    int l;
    if (b < 48) {
        l = b >> 3;
        const float* p = Wmid + (size_t)l * 65536 + (size_t)(b & 7) * 8192;
        for (int i = t; i < 8192; i += 256) m = fmaxf(m, fabsf(p[i]));
    } else {
        l = 6;
        for (int i = t; i < 4096; i += 256) m = fmaxf(m, fabsf(Win[i]));
    }
    red[t] = m; __syncthreads();
    for (int s = 128; s; s >>= 1) { if (t < s) red[t] = fmaxf(red[t], red[t + s]); __syncthreads(); }
    if (t == 0) atomicMax(&g_wmax[l], __float_as_int(red[0]));
}

// ---------------- weight prep: fp32 -> 2-digit int8 fragments ----------------
__global__ __launch_bounds__(256) void prep_kernel(
    const float* __restrict__ Wmid, const float* __restrict__ Win)
{
    int idx = blockIdx.x * 256 + threadIdx.x;
    if (idx >= PKM_TOT + 1024) return;
    bool is_in = idx >= PKM_TOT;
    int t, nt, ks, l;
    const float* W;
    if (is_in) {
        int i2 = idx - PKM_TOT;
        t = i2 & 31; nt = i2 >> 5; ks = 0; l = 6; W = Win;
    } else {
        t = idx & 31; nt = (idx >> 5) & 31; ks = (idx >> 10) & 7; l = idx >> 13;
        W = Wmid + (size_t)l * 65536;
    }
    float qs = 32384.0f / fmaxf(__int_as_float(g_wmax[l]), 1e-30f);
    int n = nt * 8 + (t >> 2);
    int kb = ks * 32 + (t & 3) * 4;
    uint32_t bh0 = 0, bh1 = 0, bl0 = 0, bl1 = 0;
#pragma unroll
    for (int r = 0; r < 4; r++) {
        int k0 = kb + r, k1 = kb + 16 + r;
        int q0 = (is_in && k0 >= 16) ? 0 : __float2int_rn(W[(size_t)k0 * DIM + n] * qs);
        int q1 = (is_in) ? 0 : __float2int_rn(W[(size_t)k1 * DIM + n] * qs);
        int h0 = (q0 + 128) >> 8, l0 = q0 - (h0 << 8);
        int h1 = (q1 + 128) >> 8, l1 = q1 - (h1 << 8);
        bh0 |= (uint32_t)(uint8_t)h0 << (r * 8);
        bl0 |= (uint32_t)(uint8_t)l0 << (r * 8);
        bh1 |= (uint32_t)(uint8_t)h1 << (r * 8);
        bl1 |= (uint32_t)(uint8_t)l1 << (r * 8);
    }
    uint4 v = make_uint4(bh0, bh1, bl0, bl1);
    if (is_in) g_pki[idx - PKM_TOT] = v;
    else       g_pkm[idx] = v;
}

// ---------------- fused model ----------------
struct SMreg {
    unsigned char ah[TILE_M * SA];   // 17408
    unsigned char al[TILE_M * SA];   // 17408
    float bias[7 * 256];             // 7168
    float wout[256];
    float part[TILE_M];
    int scl[8];
};

__global__ __launch_bounds__(256, 1) void fused_kernel(
    const float* __restrict__ x,
    const float* __restrict__ t1,
    const float* __restrict__ t2,
    const float* __restrict__ b_in,
    const float* __restrict__ b_mid,
    const float* __restrict__ W_out,
    const float* __restrict__ b_out,
    float* __restrict__ out,
    int4 res)
{
    __shared__ SMreg sm;
    int tid = threadIdx.x;
    int w = tid >> 5;
    int t = tid & 31;

    // prologue
    sm.bias[tid] = b_in[tid];
#pragma unroll
    for (int l = 0; l < N_MID; l++) sm.bias[(l + 1) * 256 + tid] = b_mid[(size_t)l * 256 + tid];
    sm.wout[tid] = W_out[tid];
    if (tid < TILE_M) sm.part[tid] = 0.0f;
    if (tid < 8) sm.scl[tid] = 0;
    __syncthreads();

    // encode: threads 0-63, one ray each
    float e[16];
    if (tid < TILE_M) {
        int ray = blockIdx.x * TILE_M + tid;
        float4 xv = ((const float4*)x)[ray];
        int rs[4] = {res.x, res.y, res.z, res.w};
        float mx = 1e-30f;
#pragma unroll
        for (int enc = 0; enc < 2; enc++) {
            float px = enc ? xv.z : xv.x;
            float py = enc ? xv.w : xv.y;
            const float* tab = enc ? t2 : t1;
#pragma unroll
            for (int l = 0; l < 4; l++) {
                float r = (float)rs[l];
                float xf0 = px * r, xf1 = py * r;
                float xi0 = floorf(xf0), xi1 = floorf(xf1);
                float fx = xf0 - xi0, fy = xf1 - xi1;
                unsigned u0 = (unsigned)xi0, u1 = (unsigned)xi1;
                const float2* T = (const float2*)(tab + (size_t)l * HASHMAP_SIZE * 2);
                unsigned b0 = u1 * PRIME1, b1 = (u1 + 1u) * PRIME1;
                float2 v00 = T[(u0 ^ b0) & HMASK];
                float2 v01 = T[(u0 ^ b1) & HMASK];
                float2 v10 = T[((u0 + 1u) ^ b0) & HMASK];
                float2 v11 = T[((u0 + 1u) ^ b1) & HMASK];
                float w00 = (1.f - fx) * (1.f - fy), w01 = (1.f - fx) * fy;
                float w10 = fx * (1.f - fy), w11 = fx * fy;
                float e0 = w00 * v00.x + w01 * v01.x + w10 * v10.x + w11 * v11.x;
                float e1 = w00 * v00.y + w01 * v01.y + w10 * v10.y + w11 * v11.y;
                e[enc * 8 + l * 2 + 0] = e0;
                e[enc * 8 + l * 2 + 1] = e1;
                mx = fmaxf(mx, fmaxf(fabsf(e0), fabsf(e1)));
            }
        }
        atomicMax(&sm.scl[0], __float_as_int(mx));
    }
    __syncthreads();
    if (tid < TILE_M) {
        float qe = 32384.0f / __int_as_float(sm.scl[0]);
        uint32_t hw[4] = {0, 0, 0, 0}, lw[4] = {0, 0, 0, 0};
#pragma unroll
        for (int j = 0; j < 16; j++) {
            int q = __float2int_rn(e[j] * qe);
            int h = (q + 128) >> 8, lo = q - (h << 8);
            hw[j >> 2] |= (uint32_t)(uint8_t)h << ((j & 3) * 8);
            lw[j >> 2] |= (uint32_t)(uint8_t)lo << ((j & 3) * 8);
        }
        uint4* ph = (uint4*)(sm.ah + tid * SA);
        uint4* pl = (uint4*)(sm.al + tid * SA);
        ph[0] = make_uint4(hw[0], hw[1], hw[2], hw[3]);
        ph[1] = make_uint4(0, 0, 0, 0);
        pl[0] = make_uint4(lw[0], lw[1], lw[2], lw[3]);
        pl[1] = make_uint4(0, 0, 0, 0);
    }
    __syncthreads();

    uint32_t ah_base = smem_u32(sm.ah) + (uint32_t)(t & 15) * SA + (uint32_t)(t >> 4) * 16;
    uint32_t al_base = smem_u32(sm.al) + (uint32_t)(t & 15) * SA + (uint32_t)(t >> 4) * 16;

    int acc1[4][4][4], acc2[4][4][4];

    for (int g = 0; g < 7; g++) {
#pragma unroll
        for (int mi = 0; mi < 4; mi++)
#pragma unroll
            for (int j = 0; j < 4; j++)
#pragma unroll
                for (int q = 0; q < 4; q++) { acc1[mi][j][q] = 0; acc2[mi][j][q] = 0; }

        int nks = (g == 0) ? 1 : 8;
#pragma unroll 1
        for (int ks = 0; ks < nks; ks++) {
            uint4 wb[4];
#pragma unroll
            for (int j = 0; j < 4; j++)
                wb[j] = (g == 0) ? g_pki[((w * 4 + j) << 5) + t]
                                 : g_pkm[((((g - 1) * 8 + ks) * 32) + (w * 4 + j)) * 32 + t];
            uint32_t af[4][4], lf[4][4];
#pragma unroll
            for (int mi = 0; mi < 4; mi++) {
                uint32_t off = (uint32_t)ks * 32 + (uint32_t)mi * (16 * SA);
                LDSM4(af[mi], ah_base + off);
                LDSM4(lf[mi], al_base + off);
            }
            if (g == 0) {
#pragma unroll
                for (int mi = 0; mi < 4; mi++)
#pragma unroll
                    for (int j = 0; j < 4; j++) MMA_S8S8(acc1[mi][j], af[mi], wb[j].x, wb[j].y);
#pragma unroll
                for (int mi = 0; mi < 4; mi++)
#pragma unroll
                    for (int j = 0; j < 4; j++) MMA_S8S8(acc2[mi][j], lf[mi], wb[j].x, wb[j].y);
#pragma unroll
                for (int mi = 0; mi < 4; mi++)
#pragma unroll
                    for (int j = 0; j < 4; j++) MMA_S8S8(acc2[mi][j], af[mi], wb[j].z, wb[j].w);
            } else {
#pragma unroll
                for (int mi = 0; mi < 4; mi++)
#pragma unroll
                    for (int j = 0; j < 4; j++) MMA_U8S8(acc1[mi][j], af[mi], wb[j].x, wb[j].y);
#pragma unroll
                for (int mi = 0; mi < 4; mi++)
#pragma unroll
                    for (int j = 0; j < 4; j++) MMA_S8S8(acc2[mi][j], lf[mi], wb[j].x, wb[j].y);
#pragma unroll
                for (int mi = 0; mi < 4; mi++)
#pragma unroll
                    for (int j = 0; j < 4; j++) MMA_U8S8(acc2[mi][j], af[mi], wb[j].z, wb[j].w);
            }
        }

        // reconstruction scale
        float wmx = __int_as_float(g_wmax[(g == 0) ? 6 : (g - 1)]);
        float si = (g == 0) ? __int_as_float(sm.scl[0]) * (1.0f / 32384.0f)
                            : __int_as_float(sm.scl[g]) * (1.0f / 65280.0f);
        float f = si * (wmx * (1.0f / 32384.0f)) * 256.0f;
        const float* bs = sm.bias + g * 256;
        int cbase = w * 32 + (t & 3) * 2;

        if (g < 6) {
            // pass 1: tile activation max
            float vmax = 0.0f;
#pragma unroll
            for (int mi = 0; mi < 4; mi++)
#pragma unroll
                for (int j = 0; j < 4; j++) {
                    int c = cbase + j * 8;
#pragma unroll
                    for (int q = 0; q < 4; q++) {
                        int cd = acc1[mi][j][q] * 256 + acc2[mi][j][q];
                        float v = fmaxf(fmaf((float)cd, f, bs[c + (q & 1)]), 0.0f);
                        vmax = fmaxf(vmax, v);
                    }
                }
            atomicMax(&sm.scl[g + 1], __float_as_int(vmax));
            __syncthreads();
            // pass 2: quantize to digits, store
            float amax = fmaxf(__int_as_float(sm.scl[g + 1]), 1e-30f);
            float qa = 65280.0f / amax;
#pragma unroll
            for (int mi = 0; mi < 4; mi++)
#pragma unroll
                for (int j = 0; j < 4; j++) {
                    int r0 = mi * 16 + (t >> 2);
                    int c = cbase + j * 8;
                    int cd0 = acc1[mi][j][0] * 256 + acc2[mi][j][0];
                    int cd1 = acc1[mi][j][1] * 256 + acc2[mi][j][1];
                    int cd2 = acc1[mi][j][2] * 256 + acc2[mi][j][2];
                    int cd3 = acc1[mi][j][3] * 256 + acc2[mi][j][3];
                    float v0 = fmaxf(fmaf((float)cd0, f, bs[c]), 0.0f);
                    float v1 = fmaxf(fmaf((float)cd1, f, bs[c + 1]), 0.0f);
                    float v2 = fmaxf(fmaf((float)cd2, f, bs[c]), 0.0f);
                    float v3 = fmaxf(fmaf((float)cd3, f, bs[c + 1]), 0.0f);
                    int A0 = __float2int_rn(v0 * qa), A1 = __float2int_rn(v1 * qa);
                    int A2 = __float2int_rn(v2 * qa), A3 = __float2int_rn(v3 * qa);
                    int h0 = (A0 + 128) >> 8, h1 = (A1 + 128) >> 8;
                    int h2 = (A2 + 128) >> 8, h3 = (A3 + 128) >> 8;
                    *(uchar2*)(sm.ah + r0 * SA + c) = make_uchar2((uint8_t)h0, (uint8_t)h1);
                    *(uchar2*)(sm.al + r0 * SA + c) =
                        make_uchar2((uint8_t)(A0 - (h0 << 8)), (uint8_t)(A1 - (h1 << 8)));
                    *(uchar2*)(sm.ah + (r0 + 8) * SA + c) = make_uchar2((uint8_t)h2, (uint8_t)h3);
                    *(uchar2*)(sm.al + (r0 + 8) * SA + c) =
                        make_uchar2((uint8_t)(A2 - (h2 << 8)), (uint8_t)(A3 - (h3 << 8)));
                }
            __syncthreads();
        } else {
            // head: relu(D + b) . W_out
#pragma unroll
            for (int mi = 0; mi < 4; mi++) {
                float s0 = 0.0f, s1 = 0.0f;
#pragma unroll
                for (int j = 0; j < 4; j++) {
                    int c = cbase + j * 8;
                    int cd0 = acc1[mi][j][0] * 256 + acc2[mi][j][0];
                    int cd1 = acc1[mi][j][1] * 256 + acc2[mi][j][1];
                    int cd2 = acc1[mi][j][2] * 256 + acc2[mi][j][2];
                    int cd3 = acc1[mi][j][3] * 256 + acc2[mi][j][3];
                    s0 += fmaxf(fmaf((float)cd0, f, bs[c]), 0.0f) * sm.wout[c]
                        + fmaxf(fmaf((float)cd1, f, bs[c + 1]), 0.0f) * sm.wout[c + 1];
                    s1 += fmaxf(fmaf((float)cd2, f, bs[c]), 0.0f) * sm.wout[c]
                        + fmaxf(fmaf((float)cd3, f, bs[c + 1]), 0.0f) * sm.wout[c + 1];
                }
                s0 += __shfl_xor_sync(0xFFFFFFFFu, s0, 1);
                s0 += __shfl_xor_sync(0xFFFFFFFFu, s0, 2);
                s1 += __shfl_xor_sync(0xFFFFFFFFu, s1, 1);
                s1 += __shfl_xor_sync(0xFFFFFFFFu, s1, 2);
                if ((t & 3) == 0) {
                    atomicAdd(&sm.part[mi * 16 + (t >> 2)], s0);
                    atomicAdd(&sm.part[mi * 16 + (t >> 2) + 8], s1);
                }
            }
            __syncthreads();
            if (tid < TILE_M)
                out[blockIdx.x * TILE_M + tid] = sm.part[tid] + b_out[0];
        }
    }
}

// ---------------- launch ----------------
extern "C" void kernel_launch(void* const* d_in, const int* in_sizes, int n_in,
                              void* d_out, int out_size)
{
    const float* x      = (const float*)d_in[0];
    const float* table1 = (const float*)d_in[1];
    const float* table2 = (const float*)d_in[2];
    const float* W_in   = (const float*)d_in[3];
    const float* b_in   = (const float*)d_in[4];
    const float* W_mid  = (const float*)d_in[5];
    const float* b_mid  = (const float*)d_in[6];
    const float* W_out  = (const float*)d_in[7];
    const float* b_out  = (const float*)d_in[8];
    float* out = (float*)d_out;

    double bgrow = exp((log(512.0) - log(16.0)) / 3.0);
    int r[4];
    for (int l = 0; l < 4; l++) r[l] = (int)floor(16.0 * pow(bgrow, (double)l));
    int4 res = make_int4(r[0], r[1], r[2], r[3]);

    wmax_kernel<<<49, 256>>>(W_mid, W_in);
    prep_kernel<<<(PKM_TOT + 1024 + 255) / 256, 256>>>(W_mid, W_in);
    fused_kernel<<<NCTAS, 256>>>(x, table1, table2, b_in, b_mid, W_out, b_out, out, res);
}

// round 9
// speedup vs baseline: 3.5397x; 3.5397x over previous
#include <cuda_runtime.h>
#include <cuda_bf16.h>
#include <cstdint>
#include <math.h>

#define N_RAYS 262144
#define HASHMAP_SIZE 524288
#define HMASK 0x7FFFFu
#define DIM 256
#define N_MID 6
#define PRIME1 2654435761u

#define TILE_M 64
#define NCTAS (N_RAYS / TILE_M)       // 4096
#define SA_B 528                      // A row stride bytes (264 bf16): conflict-free ldmatrix
#define ABUF_B (TILE_M * SA_B)        // 33792
#define AHI_OFF 0
#define ALO_OFF ABUF_B
#define BIAS_OFF (2 * ABUF_B)               // 67584
#define WOUT_OFF (BIAS_OFF + 7 * 256 * 4)   // 74752
#define PART_OFF (WOUT_OFF + 1024)          // 75776
#define SMEM_TOTAL (PART_OFF + 256)         // 76032

// fragment-packed weights: uint2 = {b0,b1} regs of mma.m16n8k16 B operand
// mid: [l(6)][kt(16)][nt(32)][lane(32)] ; in: [nt(32)][lane(32)]
#define PKM_PER_LAYER (16 * 32 * 32)        // 16384
__device__ uint2 g_pkm_hi[N_MID * PKM_PER_LAYER];
__device__ uint2 g_pkm_lo[N_MID * PKM_PER_LAYER];
__device__ uint2 g_pki_hi[32 * 32];
__device__ uint2 g_pki_lo[32 * 32];

__device__ __forceinline__ uint32_t smem_u32(const void* p) {
    uint32_t a;
    asm("{ .reg .u64 t; cvta.to.shared.u64 t, %1; cvt.u32.u64 %0, t; }" : "=r"(a) : "l"(p));
    return a;
}
__device__ __forceinline__ uint32_t pack_bf2(__nv_bfloat16 a, __nv_bfloat16 b) {
    return (uint32_t)__bfloat16_as_ushort(a) | ((uint32_t)__bfloat16_as_ushort(b) << 16);
}
__device__ __forceinline__ void split_bf(float v, __nv_bfloat16& h, __nv_bfloat16& l) {
    h = __float2bfloat16(v);
    l = __float2bfloat16(v - __bfloat162float(h));
}

#define MMA(d, a, b0v, b1v) \
    asm volatile("mma.sync.aligned.m16n8k16.row.col.f32.bf16.bf16.f32 " \
        "{%0,%1,%2,%3},{%4,%5,%6,%7},{%8,%9},{%0,%1,%2,%3};" \
        : "+f"((d)[0]), "+f"((d)[1]), "+f"((d)[2]), "+f"((d)[3]) \
        : "r"((a)[0]), "r"((a)[1]), "r"((a)[2]), "r"((a)[3]), "r"(b0v), "r"(b1v))

#define LDSM4(r, addr) \
    asm volatile("ldmatrix.sync.aligned.m8n8.x4.shared.b16 {%0,%1,%2,%3}, [%4];" \
        : "=r"((r)[0]), "=r"((r)[1]), "=r"((r)[2]), "=r"((r)[3]) : "r"(addr))

// ---------------- weight prep: fp32 -> per-thread MMA fragments (bf16 hi/lo) ----------------
#define PREP_MID (N_MID * PKM_PER_LAYER)    // 98304
#define PREP_TOT (PREP_MID + 1024)
__global__ __launch_bounds__(256) void prep_kernel(
    const float* __restrict__ Wmid, const float* __restrict__ Win)
{
    int idx = blockIdx.x * 256 + threadIdx.x;
    if (idx >= PREP_TOT) return;
    const float* W;
    int t, nt, k0base, out_idx;
    bool is_in = idx >= PREP_MID;
    if (is_in) {
        int i2 = idx - PREP_MID;
        t = i2 & 31; nt = (i2 >> 5) & 31;
        k0base = 0; W = Win; out_idx = i2;
    } else {
        t = idx & 31; nt = (idx >> 5) & 31;
        int kt = (idx >> 10) & 15; int l = idx >> 14;
        k0base = kt * 16; W = Wmid + (size_t)l * DIM * DIM; out_idx = idx;
    }
    int n = nt * 8 + (t >> 2);
    int k0 = k0base + (t & 3) * 2;
    float w00 = W[(size_t)k0 * DIM + n];
    float w01 = W[(size_t)(k0 + 1) * DIM + n];
    float w10 = W[(size_t)(k0 + 8) * DIM + n];
    float w11 = W[(size_t)(k0 + 9) * DIM + n];
    uint2 hi, lo;
    __nv_bfloat16 h0, l0, h1, l1;
    split_bf(w00, h0, l0); split_bf(w01, h1, l1);
    hi.x = pack_bf2(h0, h1); lo.x = pack_bf2(l0, l1);
    split_bf(w10, h0, l0); split_bf(w11, h1, l1);
    hi.y = pack_bf2(h0, h1); lo.y = pack_bf2(l0, l1);
    if (is_in) { g_pki_hi[out_idx] = hi; g_pki_lo[out_idx] = lo; }
    else       { g_pkm_hi[out_idx] = hi; g_pkm_lo[out_idx] = lo; }
}

// ---------------- one K=16 step: 3-term split MMA, 4 m-tiles x 4 n-tiles ----------------
__device__ __forceinline__ void do_kt(
    uint32_t kt_boff, const uint2* __restrict__ pp_hi, const uint2* __restrict__ pp_lo,
    uint32_t smAhi, uint32_t a_lane_off, float (&acc)[4][4][4])
{
    uint2 bh[4], bl[4];
#pragma unroll
    for (int j = 0; j < 4; j++) { bh[j] = pp_hi[j * 32]; bl[j] = pp_lo[j * 32]; }
    uint32_t ah[4][4], al[4][4];
#pragma unroll
    for (int mm = 0; mm < 4; mm++) {
        uint32_t addr = smAhi + a_lane_off + (uint32_t)mm * (16 * SA_B) + kt_boff;
        LDSM4(ah[mm], addr);
        LDSM4(al[mm], addr + ABUF_B);
    }
#pragma unroll
    for (int mm = 0; mm < 4; mm++)
#pragma unroll
        for (int j = 0; j < 4; j++) MMA(acc[mm][j], ah[mm], bh[j].x, bh[j].y);
#pragma unroll
    for (int mm = 0; mm < 4; mm++)
#pragma unroll
        for (int j = 0; j < 4; j++) MMA(acc[mm][j], ah[mm], bl[j].x, bl[j].y);
#pragma unroll
    for (int mm = 0; mm < 4; mm++)
#pragma unroll
        for (int j = 0; j < 4; j++) MMA(acc[mm][j], al[mm], bh[j].x, bh[j].y);
}

// ---------------- fused model ----------------
__global__ __launch_bounds__(256, 2) void fused_kernel(
    const float* __restrict__ x,
    const float* __restrict__ t1,
    const float* __restrict__ t2,
    const float* __restrict__ b_in,
    const float* __restrict__ b_mid,
    const float* __restrict__ W_out,
    const float* __restrict__ b_out,
    float* __restrict__ out,
    int4 res)
{
    extern __shared__ char smem[];
    float* sbias = (float*)(smem + BIAS_OFF);
    float* swout = (float*)(smem + WOUT_OFF);
    float* spart = (float*)(smem + PART_OFF);
    int tid = threadIdx.x;
    int w = tid >> 5;
    int t = tid & 31;

    // prologue: biases, wout, partial init
    sbias[tid] = b_in[tid];
#pragma unroll
    for (int l = 0; l < N_MID; l++) sbias[(l + 1) * 256 + tid] = b_mid[(size_t)l * 256 + tid];
    swout[tid] = W_out[tid];
    if (tid < TILE_M) spart[tid] = 0.0f;

    // encode: threads 0-63 -> row tid of A buffers (cols 0-15)
    if (tid < TILE_M) {
        int ray = blockIdx.x * TILE_M + tid;
        float4 xv = ((const float4*)x)[ray];
        int rs[4] = {res.x, res.y, res.z, res.w};
        float e[16];
#pragma unroll
        for (int enc = 0; enc < 2; enc++) {
            float px = enc ? xv.z : xv.x;
            float py = enc ? xv.w : xv.y;
            const float* tab = enc ? t2 : t1;
#pragma unroll
            for (int l = 0; l < 4; l++) {
                float r = (float)rs[l];
                float xf0 = px * r, xf1 = py * r;
                float xi0 = floorf(xf0), xi1 = floorf(xf1);
                float fx = xf0 - xi0, fy = xf1 - xi1;
                unsigned u0 = (unsigned)xi0, u1 = (unsigned)xi1;
                const float2* T = (const float2*)(tab + (size_t)l * HASHMAP_SIZE * 2);
                unsigned b0 = u1 * PRIME1, b1 = (u1 + 1u) * PRIME1;
                float2 v00 = T[(u0 ^ b0) & HMASK];
                float2 v01 = T[(u0 ^ b1) & HMASK];
                float2 v10 = T[((u0 + 1u) ^ b0) & HMASK];
                float2 v11 = T[((u0 + 1u) ^ b1) & HMASK];
                float w00 = (1.f - fx) * (1.f - fy), w01 = (1.f - fx) * fy;
                float w10 = fx * (1.f - fy), w11 = fx * fy;
                e[enc * 8 + l * 2 + 0] = w00 * v00.x + w01 * v01.x + w10 * v10.x + w11 * v11.x;
                e[enc * 8 + l * 2 + 1] = w00 * v00.y + w01 * v01.y + w10 * v10.y + w11 * v11.y;
            }
        }
        uint32_t* rh = (uint32_t*)(smem + AHI_OFF + tid * SA_B);
        uint32_t* rl = (uint32_t*)(smem + ALO_OFF + tid * SA_B);
#pragma unroll
        for (int j = 0; j < 8; j++) {
            __nv_bfloat16 h0, l0, h1, l1;
            split_bf(e[2 * j], h0, l0);
            split_bf(e[2 * j + 1], h1, l1);
            rh[j] = pack_bf2(h0, h1);
            rl[j] = pack_bf2(l0, l1);
        }
    }
    __syncthreads();

    uint32_t smAhi = smem_u32(smem);
    uint32_t a_lane_off = (uint32_t)(t & 15) * SA_B + (uint32_t)(t >> 4) * 16;

    float acc[4][4][4];

    for (int g = 0; g < 7; g++) {
#pragma unroll
        for (int m = 0; m < 4; m++)
#pragma unroll
            for (int j = 0; j < 4; j++)
#pragma unroll
                for (int q = 0; q < 4; q++) acc[m][j][q] = 0.0f;

        if (g == 0) {
            do_kt(0, g_pki_hi + w * 128 + t, g_pki_lo + w * 128 + t, smAhi, a_lane_off, acc);
        } else {
            const uint2* bh = g_pkm_hi + (size_t)(g - 1) * PKM_PER_LAYER + w * 128 + t;
            const uint2* bl = g_pkm_lo + (size_t)(g - 1) * PKM_PER_LAYER + w * 128 + t;
#pragma unroll 1
            for (int kt = 0; kt < 16; kt++)
                do_kt((uint32_t)kt * 32, bh + kt * 1024, bl + kt * 1024, smAhi, a_lane_off, acc);
        }
        __syncthreads();   // all warps done reading A

        if (g < 6) {
            const float* bs = sbias + g * 256;
#pragma unroll
            for (int m = 0; m < 4; m++) {
#pragma unroll
                for (int j = 0; j < 4; j++) {
                    int r0 = m * 16 + (t >> 2);
                    int c0 = w * 32 + j * 8 + (t & 3) * 2;
                    float v0 = fmaxf(acc[m][j][0] + bs[c0], 0.0f);
                    float v1 = fmaxf(acc[m][j][1] + bs[c0 + 1], 0.0f);
                    float v2 = fmaxf(acc[m][j][2] + bs[c0], 0.0f);
                    float v3 = fmaxf(acc[m][j][3] + bs[c0 + 1], 0.0f);
                    __nv_bfloat16 h0, l0, h1, l1;
                    split_bf(v0, h0, l0); split_bf(v1, h1, l1);
                    *(uint32_t*)(smem + AHI_OFF + r0 * SA_B + c0 * 2) = pack_bf2(h0, h1);
                    *(uint32_t*)(smem + ALO_OFF + r0 * SA_B + c0 * 2) = pack_bf2(l0, l1);
                    split_bf(v2, h0, l0); split_bf(v3, h1, l1);
                    *(uint32_t*)(smem + AHI_OFF + (r0 + 8) * SA_B + c0 * 2) = pack_bf2(h0, h1);
                    *(uint32_t*)(smem + ALO_OFF + (r0 + 8) * SA_B + c0 * 2) = pack_bf2(l0, l1);
                }
            }
            __syncthreads();
        } else {
            // output head: relu(D + b_mid[5]) . W_out + b_out
            const float* bs = sbias + 6 * 256;
#pragma unroll
            for (int m = 0; m < 4; m++) {
                float s0 = 0.0f, s1 = 0.0f;
#pragma unroll
                for (int j = 0; j < 4; j++) {
                    int c0 = w * 32 + j * 8 + (t & 3) * 2;
                    s0 += fmaxf(acc[m][j][0] + bs[c0], 0.0f) * swout[c0]
                        + fmaxf(acc[m][j][1] + bs[c0 + 1], 0.0f) * swout[c0 + 1];
                    s1 += fmaxf(acc[m][j][2] + bs[c0], 0.0f) * swout[c0]
                        + fmaxf(acc[m][j][3] + bs[c0 + 1], 0.0f) * swout[c0 + 1];
                }
                s0 += __shfl_xor_sync(0xFFFFFFFFu, s0, 1);
                s0 += __shfl_xor_sync(0xFFFFFFFFu, s0, 2);
                s1 += __shfl_xor_sync(0xFFFFFFFFu, s1, 1);
                s1 += __shfl_xor_sync(0xFFFFFFFFu, s1, 2);
                if ((t & 3) == 0) {
                    atomicAdd(&spart[m * 16 + (t >> 2)], s0);
                    atomicAdd(&spart[m * 16 + (t >> 2) + 8], s1);
                }
            }
            __syncthreads();
            if (tid < TILE_M)
                out[blockIdx.x * TILE_M + tid] = spart[tid] + b_out[0];
        }
    }
}

// ---------------- launch ----------------
extern "C" void kernel_launch(void* const* d_in, const int* in_sizes, int n_in,
                              void* d_out, int out_size)
{
    const float* x      = (const float*)d_in[0];
    const float* table1 = (const float*)d_in[1];
    const float* table2 = (const float*)d_in[2];
    const float* W_in   = (const float*)d_in[3];
    const float* b_in   = (const float*)d_in[4];
    const float* W_mid  = (const float*)d_in[5];
    const float* b_mid  = (const float*)d_in[6];
    const float* W_out  = (const float*)d_in[7];
    const float* b_out  = (const float*)d_in[8];
    float* out = (float*)d_out;

    // Replicate Python's RESOLUTIONS exactly (host libm, double precision).
    double bgrow = exp((log(512.0) - log(16.0)) / 3.0);
    int r[4];
    for (int l = 0; l < 4; l++) r[l] = (int)floor(16.0 * pow(bgrow, (double)l));
    int4 res = make_int4(r[0], r[1], r[2], r[3]);

    static bool attr_done = false;
    if (!attr_done) {
        cudaFuncSetAttribute(fused_kernel, cudaFuncAttributeMaxDynamicSharedMemorySize, SMEM_TOTAL);
        attr_done = true;
    }

    prep_kernel<<<(PREP_TOT + 255) / 256, 256>>>(W_mid, W_in);
    fused_kernel<<<NCTAS, 256, SMEM_TOTAL>>>(
        x, table1, table2, b_in, b_mid, W_out, b_out, out, res);
}